// round 9
// baseline (speedup 1.0000x reference)
#include <cuda_runtime.h>
#include <math.h>

// Problem constants (shapes fixed by the dataset)
#define NB 32
#define NA 3
#define NH 128
#define NW 128
#define NCH (NA * 6)              // 18 channels
#define NPLANE (NH * NW)          // 16384
#define NCELL (NB * NA * NPLANE)  // 1,572,864
#define EPSF 1e-7f
#define NEG_LOG_EPS 16.118095651f // -log(1e-7), the BCE clamp ceiling
#define DB 128                    // dense blocks
#define TPB 1024                  // threads per block
#define DWORK 3                   // float4 per dense thread; DB*TPB*DWORK = 393216 exactly

// Self-cleaning scratch (zero-initialized at module load; every launch restores zeros)
__device__ int    d_clr[NCELL];    // cleared-cell dedup flags
__device__ int    d_owner[NCELL];  // winning gt index + 1 per obj cell
__device__ double d_partial[DB];   // per-dense-block partial sums (plain stores)
__device__ double d_corr;          // correction sum (noobj terms at cleared cells)
__device__ double d_obj;           // obj BCE + bbox loss sum
__device__ int    d_nclr;          // # distinct cleared cells
__device__ int    d_nobj;          // # distinct obj cells (winners)
__device__ int    d_ticketA;       // phase-A completion counter
__device__ int    d_done;          // global block-completion ticket

__constant__ float c_aw[3] = {116.f, 156.f, 373.f};
__constant__ float c_ah[3] = { 90.f, 198.f, 326.f};

// precise variants (tail path, ~6k elements)
__device__ __forceinline__ float bce_neg(float v) {
    float s = 1.0f / (1.0f + expf(-v));
    float p = fminf(fmaxf(s, EPSF), 1.0f - EPSF);
    return -logf(1.0f - p);
}
__device__ __forceinline__ float bce_pos(float v) {
    float s = 1.0f / (1.0f + expf(-v));
    float p = fminf(fmaxf(s, EPSF), 1.0f - EPSF);
    return -logf(p);
}
__device__ __forceinline__ float sigmoidf_(float v) {
    return 1.0f / (1.0f + expf(-v));
}
// dense path: -log(1 - clip(sigmoid(v))) == min(softplus(v), -log(eps)).
// softplus(v) = max(v,0) + log(1 + exp(-|v|)); 2 MUFU, no RCP.
__device__ __forceinline__ float softplus_fast(float v) {
    float sp = __logf(1.0f + __expf(-fabsf(v))) + fmaxf(v, 0.0f);
    return fminf(sp, NEG_LOG_EPS);
}

// anchor IoUs + argmax for one gt box (grid units)
__device__ __forceinline__ int best_anchor(float gw, float gh,
                                           const float* awf, const float* ahf,
                                           float* ious) {
    float best = -1.0f; int bestn = 0;
#pragma unroll
    for (int a = 0; a < 3; a++) {
        float inter = fminf(gw, awf[a]) * fminf(gh, ahf[a]);
        float uni   = gw * gh + awf[a] * ahf[a] - inter;
        float iou   = inter / uni;
        ious[a] = iou;
        if (iou > best) { best = iou; bestn = a; }
    }
    return bestn;
}

__device__ __forceinline__ double warp_reduce_d(double v) {
#pragma unroll
    for (int o = 16; o > 0; o >>= 1) v += __shfl_down_sync(0xffffffffu, v, o);
    return v;
}
__device__ __forceinline__ int warp_reduce_i(int v) {
#pragma unroll
    for (int o = 16; o > 0; o >>= 1) v += __shfl_down_sync(0xffffffffu, v, o);
    return v;
}

// ---------------------------------------------------------------------------
// Single fused kernel, 132 blocks x 1024 threads (all wave-1 resident).
//   [0, gtBlocks)            : Phase A (dedup/clear + owner max)
//   [gtBlocks, gtBlocks+DB)  : dense conf-BCE sum (3 float4/thread, 32 warps/SM)
//   [gtBlocks+DB, +gtBlocks) : Phase B (spin on A, obj terms, fused cleanup)
// Epilogue: last block via ticket sums dense partials, combines, resets.
// ---------------------------------------------------------------------------
__global__ void __launch_bounds__(TPB, 1)
yolo_loss_fused(const float* __restrict__ out,
                const int*   __restrict__ gt_batch,
                const float* __restrict__ gt_boxes,
                const int*   __restrict__ size_h,
                const int*   __restrict__ size_w,
                float* __restrict__ d_out,
                int nGts, int gtBlocks) {
    const int tid  = threadIdx.x;
    const int bid  = blockIdx.x;
    const int lane = tid & 31;
    const int wid  = tid >> 5;                 // 0..31

    __shared__ double sredD[32];
    __shared__ int    sredI[32];
    __shared__ int    s_last;

    if (bid >= gtBlocks && bid < gtBlocks + DB) {
        // ---------------- dense conf-BCE sum ----------------
        const int t = (bid - gtBlocks) * TPB + tid;        // 0 .. 131071
        const float4* __restrict__ o4 = (const float4*)out;
        float acc = 0.0f;
#pragma unroll
        for (int k = 0; k < DWORK; k++) {
            const int idx   = t + k * (DB * TPB);          // 0 .. 393215
            const int plane = idx >> 12;                   // 0..95  (b*3 + a)
            const int j     = idx & 4095;
            const int b     = plane / 3;
            const int a     = plane - 3 * b;
            float4 v = o4[(size_t)(b * NCH + a * 6 + 4) * 4096 + j];
            acc += softplus_fast(v.x) + softplus_fast(v.y)
                 + softplus_fast(v.z) + softplus_fast(v.w);
        }
        double ds = warp_reduce_d((double)acc);
        if (lane == 0) sredD[wid] = ds;
        __syncthreads();
        if (wid == 0) {
            double s = warp_reduce_d(sredD[lane]);         // 32 warps -> 32 lanes
            if (lane == 0) d_partial[bid - gtBlocks] = s;  // plain store, no atomic
        }
    } else {
        // shared setup for gt phases
        const float stride_h = (float)((*size_h) / NH);
        const float stride_w = (float)((*size_w) / NW);
        float awf[3], ahf[3];
#pragma unroll
        for (int a = 0; a < 3; a++) { awf[a] = c_aw[a] / stride_w; ahf[a] = c_ah[a] / stride_h; }

        if (bid < gtBlocks) {
            // ---------------- Phase A ----------------
            const int g = bid * TPB + tid;
            double corr = 0.0;
            int nclr = 0;
            if (g < nGts) {
                const int b = gt_batch[g];
                float4 box = ((const float4*)gt_boxes)[g];
                float gx = box.x * (float)NW, gy = box.y * (float)NH;
                float gw = box.z * (float)NW, gh = box.w * (float)NH;
                int gi = (int)gx, gj = (int)gy;

                float ious[3];
                int bestn = best_anchor(gw, gh, awf, ahf, ious);
                const int cellbase = ((b * NA) * NH + gj) * NW + gi;
#pragma unroll
                for (int a = 0; a < 3; a++) {
                    if ((ious[a] > 0.5f) || (a == bestn)) {
                        int cell = cellbase + a * NPLANE;
                        if (atomicExch(&d_clr[cell], 1) == 0) {
                            float v = out[(size_t)(b * NCH + a * 6 + 4) * NPLANE + gj * NW + gi];
                            corr += (double)bce_neg(v);
                            nclr++;
                        }
                    }
                }
                atomicMax(&d_owner[cellbase + bestn * NPLANE], g + 1);
            }
            double ds = warp_reduce_d(corr);
            int    is = warp_reduce_i(nclr);
            if (lane == 0) { sredD[wid] = ds; sredI[wid] = is; }
            __syncthreads();
            if (wid == 0) {
                double s = warp_reduce_d(sredD[lane]);
                int    n = warp_reduce_i(sredI[lane]);
                if (lane == 0) {
                    if (n > 0) { atomicAdd(&d_corr, s); atomicAdd(&d_nclr, n); }
                    __threadfence();                 // release phase-A writes
                    atomicAdd(&d_ticketA, 1);        // signal phase B
                }
            }
        } else {
            // ---------------- Phase B (waits on Phase A) ----------------
            if (tid == 0) {
                while (atomicAdd(&d_ticketA, 0) < gtBlocks) { __nanosleep(64); }
            }
            __syncthreads();
            __threadfence();                     // acquire phase-A writes

            const int g = (bid - gtBlocks - DB) * TPB + tid;
            double objsum = 0.0;
            int nobj = 0;
            if (g < nGts) {
                const int b = gt_batch[g];
                float4 box = ((const float4*)gt_boxes)[g];
                float gx = box.x * (float)NW, gy = box.y * (float)NH;
                float gw = box.z * (float)NW, gh = box.w * (float)NH;
                int gi = (int)gx, gj = (int)gy;

                float ious[3];
                int bestn = best_anchor(gw, gh, awf, ahf, ious);
                const int cellbase = ((b * NA) * NH + gj) * NW + gi;
                const int cell = cellbase + bestn * NPLANE;

                if (__ldcg(&d_owner[cell]) == g + 1) {
                    const size_t base = (size_t)(b * NCH + bestn * 6) * NPLANE + gj * NW + gi;
                    float p0 = out[base];
                    float p1 = out[base + NPLANE];
                    float p2 = out[base + 2 * NPLANE];
                    float p3 = out[base + 3 * NPLANE];
                    float p4 = out[base + 4 * NPLANE];

                    float tx = gx - floorf(gx);
                    float ty = gy - floorf(gy);
                    float tw = logf(gw / awf[bestn]);
                    float th = logf(gh / ahf[bestn]);

                    float xs = sigmoidf_(p0), ys = sigmoidf_(p1);
                    float bb = (xs - tx) * (xs - tx) + (ys - ty) * (ys - ty)
                             + (p2 - tw) * (p2 - tw) + (p3 - th) * (p3 - th);
                    objsum += (double)(bb + bce_pos(p4));   // OBJ_SCALE = 1
                    nobj++;
                    d_owner[cell] = 0;   // winner cleans; losers read 0 != g+1
                }
                // cleanup dedup flags (idempotent zeroing)
#pragma unroll
                for (int a = 0; a < 3; a++) {
                    if ((ious[a] > 0.5f) || (a == bestn)) d_clr[cellbase + a * NPLANE] = 0;
                }
            }
            double ds = warp_reduce_d(objsum);
            int    is = warp_reduce_i(nobj);
            if (lane == 0) { sredD[wid] = ds; sredI[wid] = is; }
            __syncthreads();
            if (wid == 0) {
                double s = warp_reduce_d(sredD[lane]);
                int    n = warp_reduce_i(sredI[lane]);
                if (lane == 0 && n > 0) { atomicAdd(&d_obj, s); atomicAdd(&d_nobj, n); }
            }
        }
    }

    // ---------------- global completion ticket + finalize ----------------
    if (tid == 0) {
        __threadfence();
        s_last = (atomicAdd(&d_done, 1) == (int)gridDim.x - 1);
    }
    __syncthreads();
    if (s_last) {
        // parallel sum of dense partials (tid < DB each load one)
        double v = (tid < DB) ? d_partial[tid] : 0.0;
        double ds = warp_reduce_d(v);
        if (lane == 0) sredD[wid] = ds;
        __syncthreads();
        if (wid == 0) {
            double total = warp_reduce_d(sredD[lane]);
            if (lane == 0) {
                double corr  = d_corr;
                double obj   = d_obj;
                int    no    = d_nobj;
                int    ncl   = d_nclr;
                double n_obj  = (double)(no > 0 ? no : 1);
                int    nno    = NCELL - ncl;
                double n_noob = (double)(nno > 0 ? nno : 1);
                d_out[0] = (float)(obj / n_obj + 100.0 * (total - corr) / n_noob);
                // reset accumulators for the next launch (self-cleaning)
                d_corr = 0.0; d_obj = 0.0;
                d_nclr = 0; d_nobj = 0; d_ticketA = 0; d_done = 0;
            }
        }
    }
}

extern "C" void kernel_launch(void* const* d_in, const int* in_sizes, int n_in,
                              void* d_out, int out_size) {
    const float* out      = (const float*)d_in[0];
    const int*   gt_batch = (const int*)  d_in[1];
    const float* gt_boxes = (const float*)d_in[2];
    const int*   size_h   = (const int*)  d_in[3];
    const int*   size_w   = (const int*)  d_in[4];
    float* outp = (float*)d_out;
    const int nGts = in_sizes[1];

    const int gtBlocks = (nGts + TPB - 1) / TPB;   // 2 for nGts=1920
    const int grid = gtBlocks + DB + gtBlocks;     // 132 blocks, all wave-1 resident
    yolo_loss_fused<<<grid, TPB>>>(out, gt_batch, gt_boxes,
                                   size_h, size_w, outp, nGts, gtBlocks);
}

// round 11
// speedup vs baseline: 1.4147x; 1.4147x over previous
#include <cuda_runtime.h>
#include <math.h>

// Problem constants (shapes fixed by the dataset)
#define NB 32
#define NA 3
#define NH 128
#define NW 128
#define NCH (NA * 6)              // 18 channels
#define NPLANE (NH * NW)          // 16384
#define NCELL (NB * NA * NPLANE)  // 1,572,864
#define EPSF 1e-7f
#define NEG_LOG_EPS 16.118095651f // -log(1e-7), the BCE clamp ceiling
#define DENSE_BLOCKS 1536         // 1536 x 256 x 1 float4 = 393216 exactly

// Self-cleaning scratch (zero-initialized at module load; every launch restores zeros)
__device__ int    d_clr[NCELL];    // cleared-cell dedup flags
__device__ int    d_owner[NCELL];  // winning gt index + 1 per obj cell
__device__ double d_total;         // dense noobj-BCE sum over ALL cells
__device__ double d_corr;          // correction sum (noobj terms at cleared cells)
__device__ double d_obj;           // obj BCE + bbox loss sum (takeover-telescoped)
__device__ int    d_nclr;          // # distinct cleared cells
__device__ int    d_nobj;          // # distinct obj cells

__constant__ float c_aw[3] = {116.f, 156.f, 373.f};
__constant__ float c_ah[3] = { 90.f, 198.f, 326.f};

// precise variants (sparse path, few thousand evals)
__device__ __forceinline__ float bce_neg(float v) {
    float s = 1.0f / (1.0f + expf(-v));
    float p = fminf(fmaxf(s, EPSF), 1.0f - EPSF);
    return -logf(1.0f - p);
}
__device__ __forceinline__ float bce_pos(float v) {
    float s = 1.0f / (1.0f + expf(-v));
    float p = fminf(fmaxf(s, EPSF), 1.0f - EPSF);
    return -logf(p);
}
__device__ __forceinline__ float sigmoidf_(float v) {
    return 1.0f / (1.0f + expf(-v));
}
// dense path: -log(1 - clip(sigmoid(v))) == min(softplus(v), -log(eps)); 2 MUFU.
__device__ __forceinline__ float softplus_fast(float v) {
    float sp = __logf(1.0f + __expf(-fabsf(v))) + fmaxf(v, 0.0f);
    return fminf(sp, NEG_LOG_EPS);
}

// anchor IoUs + argmax for one gt box (grid units)
__device__ __forceinline__ int best_anchor(float gw, float gh,
                                           const float* awf, const float* ahf,
                                           float* ious) {
    float best = -1.0f; int bestn = 0;
#pragma unroll
    for (int a = 0; a < 3; a++) {
        float inter = fminf(gw, awf[a]) * fminf(gh, ahf[a]);
        float uni   = gw * gh + awf[a] * ahf[a] - inter;
        float iou   = inter / uni;
        ious[a] = iou;
        if (iou > best) { best = iou; bestn = a; }
    }
    return bestn;
}

__device__ __forceinline__ double warp_reduce_d(double v) {
#pragma unroll
    for (int o = 16; o > 0; o >>= 1) v += __shfl_down_sync(0xffffffffu, v, o);
    return v;
}
__device__ __forceinline__ int warp_reduce_i(int v) {
#pragma unroll
    for (int o = 16; o > 0; o >>= 1) v += __shfl_down_sync(0xffffffffu, v, o);
    return v;
}

// Obj term for one (cell, gt-box) pair. __noinline__ so both call sites
// (adder and subtractor) execute identical code -> exact double telescoping.
__device__ __noinline__ double obj_term(const float* __restrict__ out,
                                        int b, int bestn, int gi, int gj,
                                        float gx, float gy, float gw, float gh,
                                        float aw, float ah) {
    const size_t base = (size_t)(b * NCH + bestn * 6) * NPLANE + gj * NW + gi;
    float p0 = out[base];
    float p1 = out[base + NPLANE];
    float p2 = out[base + 2 * NPLANE];
    float p3 = out[base + 3 * NPLANE];
    float p4 = out[base + 4 * NPLANE];
    float tx = gx - floorf(gx);
    float ty = gy - floorf(gy);
    float tw = logf(gw / aw);
    float th = logf(gh / ah);
    float xs = sigmoidf_(p0), ys = sigmoidf_(p1);
    float bb = (xs - tx) * (xs - tx) + (ys - ty) * (ys - ty)
             + (p2 - tw) * (p2 - tw) + (p3 - th) * (p3 - th);
    return (double)(bb + bce_pos(p4));   // OBJ_SCALE = 1
}

// ---------------------------------------------------------------------------
// K1: blocks [0, gtBlocks)  : single-pass GT phase (dedup/corr + owner takeover)
//     blocks [gtBlocks, +DENSE_BLOCKS) : dense conf-BCE sum (1 float4/thread)
// No inter-block dependencies anywhere.
// ---------------------------------------------------------------------------
__global__ void k1_dense_gt(const float* __restrict__ out,
                            const int*   __restrict__ gt_batch,
                            const float* __restrict__ gt_boxes,
                            const int*   __restrict__ size_h,
                            const int*   __restrict__ size_w,
                            int nGts, int gtBlocks) {
    const int tid  = threadIdx.x;
    const int bid  = blockIdx.x;
    const int lane = tid & 31;
    const int wid  = tid >> 5;

    __shared__ double sredD[8];
    __shared__ int    sredI[8];

    if (bid >= gtBlocks) {
        // ---------------- dense conf-BCE sum ----------------
        const int idx = (bid - gtBlocks) * 256 + tid;      // 0 .. 393215
        const float4* __restrict__ o4 = (const float4*)out;
        const int plane = idx >> 12;                       // 0..95  (b*3 + a)
        const int j     = idx & 4095;
        const int b     = plane / 3;
        const int a     = plane - 3 * b;
        float4 v = o4[(size_t)(b * NCH + a * 6 + 4) * 4096 + j];
        float s = softplus_fast(v.x) + softplus_fast(v.y)
                + softplus_fast(v.z) + softplus_fast(v.w);

        double ds = warp_reduce_d((double)s);
        if (lane == 0) sredD[wid] = ds;
        __syncthreads();
        if (wid == 0) {
            double t = (lane < 8) ? sredD[lane] : 0.0;
#pragma unroll
            for (int o = 4; o > 0; o >>= 1) t += __shfl_down_sync(0xffu, t, o);
            if (lane == 0) atomicAdd(&d_total, t);
        }
        return;
    }

    // ---------------- GT phase: one gt per thread, single pass ----------------
    const float stride_h = (float)((*size_h) / NH);
    const float stride_w = (float)((*size_w) / NW);
    float awf[3], ahf[3];
#pragma unroll
    for (int a = 0; a < 3; a++) { awf[a] = c_aw[a] / stride_w; ahf[a] = c_ah[a] / stride_h; }

    const int g = bid * 256 + tid;
    double corr = 0.0, objsum = 0.0;
    int nclr = 0, nobj = 0;
    if (g < nGts) {
        const int b = gt_batch[g];
        float4 box = ((const float4*)gt_boxes)[g];
        float gx = box.x * (float)NW, gy = box.y * (float)NH;
        float gw = box.z * (float)NW, gh = box.w * (float)NH;
        int gi = (int)gx, gj = (int)gy;

        float ious[3];
        int bestn = best_anchor(gw, gh, awf, ahf, ious);
        const int cellbase = ((b * NA) * NH + gj) * NW + gi;

        // dedup clear + correction terms
#pragma unroll
        for (int a = 0; a < 3; a++) {
            if ((ious[a] > 0.5f) || (a == bestn)) {
                int cell = cellbase + a * NPLANE;
                if (atomicExch(&d_clr[cell], 1) == 0) {
                    float v = out[(size_t)(b * NCH + a * 6 + 4) * NPLANE + gj * NW + gi];
                    corr += (double)bce_neg(v);
                    nclr++;
                }
            }
        }

        // owner takeover accounting: telescopes to final winner's term
        const int cell = cellbase + bestn * NPLANE;
        int old = atomicMax(&d_owner[cell], g + 1);
        if (old < g + 1) {
            objsum += obj_term(out, b, bestn, gi, gj, gx, gy, gw, gh,
                               awf[bestn], ahf[bestn]);
            if (old == 0) {
                nobj++;
            } else {
                // displaced gt old-1 maps to the SAME cell (same owner address)
                float4 obox = ((const float4*)gt_boxes)[old - 1];
                float ogx = obox.x * (float)NW, ogy = obox.y * (float)NH;
                float ogw = obox.z * (float)NW, ogh = obox.w * (float)NH;
                objsum -= obj_term(out, b, bestn, gi, gj, ogx, ogy, ogw, ogh,
                                   awf[bestn], ahf[bestn]);
            }
        }
    }

    double dsC = warp_reduce_d(corr);
    double dsO = warp_reduce_d(objsum);
    int    isC = warp_reduce_i(nclr);
    int    isO = warp_reduce_i(nobj);
    if (lane == 0) { sredD[wid] = dsC; sredI[wid] = isC; }
    __syncthreads();
    if (wid == 0) {
        double s = (lane < 8) ? sredD[lane] : 0.0;
        int    n = (lane < 8) ? sredI[lane] : 0;
#pragma unroll
        for (int o = 4; o > 0; o >>= 1) {
            s += __shfl_down_sync(0xffu, s, o);
            n += __shfl_down_sync(0xffu, n, o);
        }
        if (lane == 0 && n > 0) { atomicAdd(&d_corr, s); atomicAdd(&d_nclr, n); }
    }
    __syncthreads();
    if (lane == 0) { sredD[wid] = dsO; sredI[wid] = isO; }
    __syncthreads();
    if (wid == 0) {
        double s = (lane < 8) ? sredD[lane] : 0.0;
        int    n = (lane < 8) ? sredI[lane] : 0;
#pragma unroll
        for (int o = 4; o > 0; o >>= 1) {
            s += __shfl_down_sync(0xffu, s, o);
            n += __shfl_down_sync(0xffu, n, o);
        }
        if (lane == 0) {
            if (s != 0.0) atomicAdd(&d_obj, s);
            if (n > 0)    atomicAdd(&d_nobj, n);
        }
    }
}

// ---------------------------------------------------------------------------
// K2: blocks [0, gtBlocks) : cleanup (zero touched d_clr / d_owner cells)
//     block gtBlocks       : finalize scalar + reset accumulators
// (cleanup and finalize touch disjoint state; no ordering needed)
// ---------------------------------------------------------------------------
__global__ void k2_cleanup_finalize(const int*   __restrict__ gt_batch,
                                    const float* __restrict__ gt_boxes,
                                    const int*   __restrict__ size_h,
                                    const int*   __restrict__ size_w,
                                    float* __restrict__ d_out,
                                    int nGts, int gtBlocks) {
    const int tid = threadIdx.x;
    const int bid = blockIdx.x;

    if (bid < gtBlocks) {
        const float stride_h = (float)((*size_h) / NH);
        const float stride_w = (float)((*size_w) / NW);
        float awf[3], ahf[3];
#pragma unroll
        for (int a = 0; a < 3; a++) { awf[a] = c_aw[a] / stride_w; ahf[a] = c_ah[a] / stride_h; }

        const int g = bid * 256 + tid;
        if (g < nGts) {
            const int b = gt_batch[g];
            float4 box = ((const float4*)gt_boxes)[g];
            float gw = box.z * (float)NW, gh = box.w * (float)NH;
            int gi = (int)(box.x * (float)NW), gj = (int)(box.y * (float)NH);

            float ious[3];
            int bestn = best_anchor(gw, gh, awf, ahf, ious);
            const int cellbase = ((b * NA) * NH + gj) * NW + gi;
#pragma unroll
            for (int a = 0; a < 3; a++) {
                if ((ious[a] > 0.5f) || (a == bestn)) d_clr[cellbase + a * NPLANE] = 0;
            }
            d_owner[cellbase + bestn * NPLANE] = 0;
        }
    } else if (tid == 0) {
        double total = d_total;
        double corr  = d_corr;
        double obj   = d_obj;
        int    no    = d_nobj;
        int    ncl   = d_nclr;
        double n_obj  = (double)(no > 0 ? no : 1);
        int    nno    = NCELL - ncl;
        double n_noob = (double)(nno > 0 ? nno : 1);
        d_out[0] = (float)(obj / n_obj + 100.0 * (total - corr) / n_noob);
        // reset accumulators for the next launch (self-cleaning)
        d_total = 0.0; d_corr = 0.0; d_obj = 0.0;
        d_nclr = 0; d_nobj = 0;
    }
}

extern "C" void kernel_launch(void* const* d_in, const int* in_sizes, int n_in,
                              void* d_out, int out_size) {
    const float* out      = (const float*)d_in[0];
    const int*   gt_batch = (const int*)  d_in[1];
    const float* gt_boxes = (const float*)d_in[2];
    const int*   size_h   = (const int*)  d_in[3];
    const int*   size_w   = (const int*)  d_in[4];
    float* outp = (float*)d_out;
    const int nGts = in_sizes[1];

    const int gtBlocks = (nGts + 255) / 256;   // 8 for nGts=1920
    k1_dense_gt<<<gtBlocks + DENSE_BLOCKS, 256>>>(out, gt_batch, gt_boxes,
                                                  size_h, size_w, nGts, gtBlocks);
    k2_cleanup_finalize<<<gtBlocks + 1, 256>>>(gt_batch, gt_boxes,
                                               size_h, size_w, outp, nGts, gtBlocks);
}